// round 3
// baseline (speedup 1.0000x reference)
#include <cuda_runtime.h>
#include <cuda_bf16.h>
#include <cstdint>

// ---------------- problem constants ----------------
namespace {
constexpr int H_    = 10;
constexpr int NROWS = 100000;
constexpr int F_    = 256;
constexpr int HIDD  = 512;
constexpr int C_    = 47;

constexpr int BM = 128, BN = 128, BK = 32;      // K-tile = 32 (two k16 mma chunks)
constexpr int APAIRS = BK / 2;                  // 16 bf16x2 pairs per row per tile
constexpr int ASTR = 20;    // words per A smem row  (16 pairs + pad; conflict-free frag LDS)
constexpr int BSTR = 136;   // words per B smem pair-row (128 cols + pad; conflict-free)
constexpr int AWORDS = BM * ASTR;               // 2560
constexpr int BWORDS = APAIRS * BSTR;           // 2176
constexpr int BUFWORDS = 2 * AWORDS + 2 * BWORDS;   // AH, AL, BH, BL
constexpr int SMEM_DYN = 2 * BUFWORDS * 4;      // double buffered: 75776 B
}

// ---------------- scratch ----------------
__device__ float g_S1[(size_t)NROWS * HIDD];
__device__ float g_S2[(size_t)NROWS * HIDD];
__device__ float g_S3[(size_t)NROWS * HIDD];

// ---------------- helpers ----------------
__device__ __forceinline__ unsigned pack_bf2(__nv_bfloat16 lo_k, __nv_bfloat16 hi_k) {
    unsigned u0 = (unsigned)__bfloat16_as_ushort(lo_k);
    unsigned u1 = (unsigned)__bfloat16_as_ushort(hi_k);
    return u0 | (u1 << 16);
}

// split (f0,f1) -> packed hi pair + packed lo pair (bf16 hi/lo decomposition)
__device__ __forceinline__ void split2(float f0, float f1, unsigned& hi, unsigned& lo) {
    __nv_bfloat16 h0 = __float2bfloat16(f0);
    __nv_bfloat16 h1 = __float2bfloat16(f1);
    float r0 = f0 - __bfloat162float(h0);
    float r1 = f1 - __bfloat162float(h1);
    hi = pack_bf2(h0, h1);
    lo = pack_bf2(__float2bfloat16(r0), __float2bfloat16(r1));
}

__device__ __forceinline__ void mma_bf16(float* c, const unsigned* a, unsigned b0, unsigned b1) {
    asm volatile(
        "mma.sync.aligned.m16n8k16.row.col.f32.bf16.bf16.f32 "
        "{%0,%1,%2,%3},{%4,%5,%6,%7},{%8,%9},{%0,%1,%2,%3};"
        : "+f"(c[0]), "+f"(c[1]), "+f"(c[2]), "+f"(c[3])
        : "r"(a[0]), "r"(a[1]), "r"(a[2]), "r"(a[3]), "r"(b0), "r"(b1));
}

// ============================================================================
// Fused recursive attention (unchanged; DRAM-bound, ~optimal)
// ============================================================================
__global__ __launch_bounds__(256)
void att_kernel(const float* __restrict__ feat, const float* __restrict__ wa,
                const float* __restrict__ ba_p, float* __restrict__ right)
{
    const int gw   = (blockIdx.x * blockDim.x + threadIdx.x) >> 5;
    const int lane = threadIdx.x & 31;
    if (gw >= NROWS) return;

    const float ba = __ldg(ba_p);

    float wlv[8], wrv[8];
#pragma unroll
    for (int j = 0; j < 8; j++) {
        wlv[j] = __ldg(wa + lane + 32 * j);
        wrv[j] = __ldg(wa + F_ + lane + 32 * j);
    }

    float v[H_][8];
    const float* base = feat + (size_t)gw * F_ + lane;
#pragma unroll
    for (int h = 0; h < H_; h++) {
        const float* p = base + (size_t)h * NROWS * F_;
#pragma unroll
        for (int j = 0; j < 8; j++) v[h][j] = p[32 * j];
    }

    float xl[H_], xr[H_];
#pragma unroll
    for (int h = 0; h < H_; h++) {
        float sl = 0.f, sr = 0.f;
#pragma unroll
        for (int j = 0; j < 8; j++) { sl = fmaf(v[h][j], wlv[j], sl); sr = fmaf(v[h][j], wrv[j], sr); }
#pragma unroll
        for (int o = 16; o; o >>= 1) {
            sl += __shfl_xor_sync(0xffffffffu, sl, o);
            sr += __shfl_xor_sync(0xffffffffu, sr, o);
        }
        xl[h] = sl; xr[h] = sr;
    }

    float s[H_];
    { float t = xl[0] + xr[0] + ba; s[0] = t >= 0.f ? t : 0.2f * t; }
#pragma unroll
    for (int i = 1; i < H_; i++) {
        float m = s[0];
        for (int h2 = 1; h2 < i; h2++) m = fmaxf(m, s[h2]);
        float den = 0.f, num = 0.f;
        for (int h2 = 0; h2 < i; h2++) {
            float e = __expf(s[h2] - m);
            den += e; num = fmaf(e, xl[h2], num);
        }
        float t = num / den + xr[i] + ba;
        s[i] = t >= 0.f ? t : 0.2f * t;
    }

    float m = s[0];
#pragma unroll
    for (int h2 = 1; h2 < H_; h2++) m = fmaxf(m, s[h2]);
    float e[H_], den = 0.f;
#pragma unroll
    for (int h2 = 0; h2 < H_; h2++) { e[h2] = __expf(s[h2] - m); den += e[h2]; }
    const float inv = 1.f / den;

    float* rp = right + (size_t)gw * F_ + lane;
#pragma unroll
    for (int j = 0; j < 8; j++) {
        float acc = 0.f;
#pragma unroll
        for (int h2 = 0; h2 < H_; h2++) acc = fmaf(e[h2] * inv, v[h2][j], acc);
        rp[32 * j] = acc;
    }
}

// ============================================================================
// bf16x3 GEMM (m16n8k16), double-buffered smem, fused A-transform + epilogue.
// ATR: 0 none | 1 prelu(alpha) | 2 support = 0.5*prelu(A,alpha)+0.5*A2
// EPI: 0 D=v+bias | 1 D=prelu(v+bias,alpha) | 2 D=v+prelu(X,alpha) | 3 D=X+v+bias
// ============================================================================
template<int ATR, int EPI>
__global__ __launch_bounds__(256)
void gemm_kernel(const float* __restrict__ A, const float* __restrict__ A2,
                 const float* __restrict__ B, const float* __restrict__ bias,
                 float* __restrict__ D, const float* __restrict__ X,
                 const float* __restrict__ alpha_p,
                 int M, int Nc, int K)
{
    extern __shared__ unsigned sh[];

    const int tid  = threadIdx.x;
    const int warp = tid >> 5, lane = tid & 31;
    const int wr = warp >> 1, wc = warp & 1;
    const int g = lane >> 2, t4 = lane & 3;
    const int rowBase = blockIdx.y * BM;
    const int colBase = blockIdx.x * BN;

    float alpha = 0.f;
    if (ATR == 1 || ATR == 2 || EPI == 1 || EPI == 2) alpha = __ldg(alpha_p);

    // staging thread mapping
    const int rA  = tid >> 4;    // 0..15 : A row base (rows rA+16j)
    const int pA  = tid & 15;    // 0..15 : A k-pair
    const int cB  = tid & 127;   // 0..127: B col
    const int pB0 = tid >> 7;    // 0..1  : B k-pair base (pairs pB0+2j)

    float acc[2][8][4];
#pragma unroll
    for (int mi = 0; mi < 2; mi++)
#pragma unroll
        for (int ni = 0; ni < 8; ni++)
#pragma unroll
            for (int q = 0; q < 4; q++) acc[mi][ni][q] = 0.f;

    float aF0[8], aF1[8], bF0[8], bF1[8];
    const int ktiles = (K + BK - 1) / BK;

    auto elemA = [&](int rr, int cc) -> float {
        size_t idx = (size_t)rr * K + cc;
        if (ATR == 0) return A[idx];
        if (ATR == 1) { float x = A[idx]; return x >= 0.f ? x : alpha * x; }
        float x = A[idx], h = A2[idx];
        float xi = x >= 0.f ? x : alpha * x;
        return 0.5f * xi + 0.5f * h;
    };

    auto loadAB = [&](int k0) {
#pragma unroll
        for (int j = 0; j < 8; j++) {
            int rr = rowBase + rA + 16 * j;
            int c0 = k0 + 2 * pA;
            float v0 = 0.f, v1 = 0.f;
            if (rr < M) {
                if (c0 < K)     v0 = elemA(rr, c0);
                if (c0 + 1 < K) v1 = elemA(rr, c0 + 1);
            }
            aF0[j] = v0; aF1[j] = v1;
        }
#pragma unroll
        for (int j = 0; j < 8; j++) {
            int p = pB0 + 2 * j;
            int r0 = k0 + 2 * p;
            int cc = colBase + cB;
            float v0 = 0.f, v1 = 0.f;
            if (cc < Nc) {
                if (r0 < K)     v0 = B[(size_t)r0 * Nc + cc];
                if (r0 + 1 < K) v1 = B[(size_t)(r0 + 1) * Nc + cc];
            }
            bF0[j] = v0; bF1[j] = v1;
        }
    };

    auto stage = [&](int buf) {
        unsigned* aH = sh + buf * BUFWORDS;
        unsigned* aL = aH + AWORDS;
        unsigned* bH = aL + AWORDS;
        unsigned* bL = bH + BWORDS;
#pragma unroll
        for (int j = 0; j < 8; j++) {
            unsigned hi, lo; split2(aF0[j], aF1[j], hi, lo);
            int r = rA + 16 * j;
            aH[r * ASTR + pA] = hi;
            aL[r * ASTR + pA] = lo;
        }
#pragma unroll
        for (int j = 0; j < 8; j++) {
            unsigned hi, lo; split2(bF0[j], bF1[j], hi, lo);
            int p = pB0 + 2 * j;
            bH[p * BSTR + cB] = hi;   // fully coalesced, conflict-free STS
            bL[p * BSTR + cB] = lo;
        }
    };

    auto compute = [&](int buf) {
        const unsigned* aH = sh + buf * BUFWORDS;
        const unsigned* aL = aH + AWORDS;
        const unsigned* bH = aL + AWORDS;
        const unsigned* bL = bH + BWORDS;
#pragma unroll
        for (int kk = 0; kk < 2; kk++) {
            unsigned ah[2][4], al[2][4];
#pragma unroll
            for (int mi = 0; mi < 2; mi++) {
                int r = wr * 32 + mi * 16 + g;
                int p0 = kk * 8 + t4;
                ah[mi][0] = aH[r * ASTR + p0];
                ah[mi][1] = aH[(r + 8) * ASTR + p0];
                ah[mi][2] = aH[r * ASTR + p0 + 4];
                ah[mi][3] = aH[(r + 8) * ASTR + p0 + 4];
                al[mi][0] = aL[r * ASTR + p0];
                al[mi][1] = aL[(r + 8) * ASTR + p0];
                al[mi][2] = aL[r * ASTR + p0 + 4];
                al[mi][3] = aL[(r + 8) * ASTR + p0 + 4];
            }
#pragma unroll
            for (int ni = 0; ni < 8; ni++) {
                int cb = wc * 64 + ni * 8 + g;
                int p0 = kk * 8 + t4;
                unsigned bh0 = bH[p0 * BSTR + cb];
                unsigned bh1 = bH[(p0 + 4) * BSTR + cb];
                unsigned bl0 = bL[p0 * BSTR + cb];
                unsigned bl1 = bL[(p0 + 4) * BSTR + cb];
#pragma unroll
                for (int mi = 0; mi < 2; mi++) {
                    mma_bf16(acc[mi][ni], ah[mi], bh0, bh1);  // hi*hi
                    mma_bf16(acc[mi][ni], ah[mi], bl0, bl1);  // hi*lo
                    mma_bf16(acc[mi][ni], al[mi], bh0, bh1);  // lo*hi
                }
            }
        }
    };

    // ---- pipelined mainloop: one sync per K-tile, loads one tile ahead ----
    loadAB(0);
    stage(0);
    __syncthreads();
    if (ktiles > 1) loadAB(BK);

    for (int kt = 0; kt < ktiles; kt++) {
        compute(kt & 1);
        if (kt + 1 < ktiles) {
            stage((kt + 1) & 1);
            __syncthreads();
            if (kt + 2 < ktiles) loadAB((kt + 2) * BK);
        }
    }

    // ---- epilogue ----
#pragma unroll
    for (int mi = 0; mi < 2; mi++) {
#pragma unroll
        for (int ni = 0; ni < 8; ni++) {
            int r0 = rowBase + wr * 32 + mi * 16 + g;
            int c0 = colBase + wc * 64 + ni * 8 + 2 * t4;
#pragma unroll
            for (int q = 0; q < 4; q++) {
                int r = r0 + (q >= 2 ? 8 : 0);
                int c = c0 + (q & 1);
                if (r < M && c < Nc) {
                    float v = acc[mi][ni][q];
                    size_t idx = (size_t)r * Nc + c;
                    if (EPI == 0) {
                        D[idx] = v + __ldg(bias + c);
                    } else if (EPI == 1) {
                        float t = v + __ldg(bias + c);
                        D[idx] = t >= 0.f ? t : alpha * t;
                    } else if (EPI == 2) {
                        float xv = X[idx];
                        float xi = xv >= 0.f ? xv : alpha * xv;
                        D[idx] = v + xi;
                    } else {
                        D[idx] = X[idx] + v + __ldg(bias + c);
                    }
                }
            }
        }
    }
}

// ============================================================================
extern "C" void kernel_launch(void* const* d_in, const int* in_sizes, int n_in,
                              void* d_out, int out_size)
{
    (void)in_sizes; (void)n_in; (void)out_size;

    const float* features  = (const float*)d_in[0];
    const float* label_emb = (const float*)d_in[1];
    const float* wa        = (const float*)d_in[2];
    const float* ba        = (const float*)d_in[3];
    const float* w0        = (const float*)d_in[4];
    const float* b0        = (const float*)d_in[5];
    const float* wg1       = (const float*)d_in[6];
    const float* wg2       = (const float*)d_in[7];
    const float* w_last    = (const float*)d_in[8];
    const float* b_last    = (const float*)d_in[9];
    const float* a_out     = (const float*)d_in[10];
    const float* wl0       = (const float*)d_in[11];
    const float* bl0       = (const float*)d_in[12];
    const float* wl1       = (const float*)d_in[13];
    const float* bl1       = (const float*)d_in[14];
    const float* wl2       = (const float*)d_in[15];
    const float* bl2       = (const float*)d_in[16];
    const float* wl3       = (const float*)d_in[17];
    const float* bl3       = (const float*)d_in[18];
    const float* a_lab     = (const float*)d_in[19];
    float* out = (float*)d_out;

    float *S1, *S2, *S3;
    cudaGetSymbolAddress((void**)&S1, g_S1);
    cudaGetSymbolAddress((void**)&S2, g_S2);
    cudaGetSymbolAddress((void**)&S3, g_S3);

    // allow >48KB dynamic smem (host-side attribute set; not a stream op)
    cudaFuncSetAttribute(gemm_kernel<0,1>, cudaFuncAttributeMaxDynamicSharedMemorySize, SMEM_DYN);
    cudaFuncSetAttribute(gemm_kernel<0,0>, cudaFuncAttributeMaxDynamicSharedMemorySize, SMEM_DYN);
    cudaFuncSetAttribute(gemm_kernel<2,2>, cudaFuncAttributeMaxDynamicSharedMemorySize, SMEM_DYN);
    cudaFuncSetAttribute(gemm_kernel<1,3>, cudaFuncAttributeMaxDynamicSharedMemorySize, SMEM_DYN);

    dim3 blk(256);
    dim3 gAtt((NROWS + 7) / 8);
    dim3 g512((HIDD + BN - 1) / BN, (NROWS + BM - 1) / BM);   // (4, 782)
    dim3 g47(1, (NROWS + BM - 1) / BM);

    // attention -> right in S3 (N x 256)
    att_kernel<<<gAtt, blk>>>(features, wa, ba, S3);

    // label branch: S1/S2 ping-pong, final into out
    gemm_kernel<0,1><<<g512, blk, SMEM_DYN>>>(label_emb, nullptr, wl0, bl0, S1, nullptr, a_lab, NROWS, HIDD, C_);
    gemm_kernel<0,1><<<g512, blk, SMEM_DYN>>>(S1, nullptr, wl1, bl1, S2, nullptr, a_lab, NROWS, HIDD, HIDD);
    gemm_kernel<0,1><<<g512, blk, SMEM_DYN>>>(S2, nullptr, wl2, bl2, S1, nullptr, a_lab, NROWS, HIDD, HIDD);
    gemm_kernel<0,0><<<g47 , blk, SMEM_DYN>>>(S1, nullptr, wl3, bl3, out, nullptr, nullptr, NROWS, C_, HIDD);

    // feature branch
    gemm_kernel<0,0><<<g512, blk, SMEM_DYN>>>(S3, nullptr, w0, b0, S2, nullptr, nullptr, NROWS, HIDD, F_);
    gemm_kernel<2,2><<<g512, blk, SMEM_DYN>>>(S2, S2, wg1, nullptr, S1, S2, a_out, NROWS, HIDD, HIDD);
    gemm_kernel<2,2><<<g512, blk, SMEM_DYN>>>(S1, S2, wg2, nullptr, S3, S1, a_out, NROWS, HIDD, HIDD);
    gemm_kernel<1,3><<<g47 , blk, SMEM_DYN>>>(S3, nullptr, w_last, b_last, out, out, a_out, NROWS, C_, HIDD);
}

// round 8
// speedup vs baseline: 2.2038x; 2.2038x over previous
#include <cuda_runtime.h>
#include <cuda_bf16.h>
#include <cstdint>

// ---------------- problem constants ----------------
namespace {
constexpr int H_    = 10;
constexpr int NROWS = 100000;
constexpr int MPAD  = 100096;            // 782 * 128
constexpr int F_    = 256;
constexpr int HIDD  = 512;
constexpr int C_    = 47;
constexpr int HIDDW = HIDD / 2;          // 256 words per activation row

constexpr int BK    = 32;                // K elements per tile = 16 k-pair words
constexpr int ASTR  = 20;                // smem row stride in words (16 pairs + pad)
constexpr int COMPW = 128 * ASTR;        // 2560 words per component
constexpr int BUFW  = 4 * COMPW;         // Ahi,Alo,Bhi,Blo = 10240 words
constexpr int SMEM_DYN = 2 * BUFW * 4;   // 81920 B double-buffered

// packed-weight offsets in WORDS, layout [Npad][Kpad2] (n-major rows of k-pair words)
constexpr size_t O_wl0   = 0;            // 512 x 32  = 16384
constexpr size_t O_wl1   = 16384;        // 512 x 256 = 131072
constexpr size_t O_wl2   = 147456;       // 131072
constexpr size_t O_wl3   = 278528;       // 128 x 256 = 32768
constexpr size_t O_w0    = 311296;       // 512 x 128 = 65536
constexpr size_t O_wg1   = 376832;       // 131072
constexpr size_t O_wg2   = 507904;       // 131072
constexpr size_t O_wlast = 638976;       // 32768
constexpr size_t W_WORDS = 671744;
}

// ---------------- device scratch (word-typed => 4B+ alignment guaranteed) ----
__device__ uint32_t g_Wph[W_WORDS];
__device__ uint32_t g_Wpl[W_WORDS];
__device__ uint32_t g_L0h[(size_t)MPAD * 32];
__device__ uint32_t g_L0l[(size_t)MPAD * 32];
__device__ uint32_t g_Ah[(size_t)MPAD * HIDDW];
__device__ uint32_t g_Al[(size_t)MPAD * HIDDW];
__device__ uint32_t g_Bh[(size_t)MPAD * HIDDW];
__device__ uint32_t g_Bl[(size_t)MPAD * HIDDW];
__device__ uint32_t g_Rh[(size_t)MPAD * 128];
__device__ uint32_t g_Rl[(size_t)MPAD * 128];
__device__ float g_X1[(size_t)MPAD * HIDD];
__device__ float g_X2[(size_t)MPAD * HIDD];

// ---------------- helpers ----------------
__device__ __forceinline__ void splitf(float f, __nv_bfloat16& h, __nv_bfloat16& l) {
    h = __float2bfloat16(f);
    l = __float2bfloat16(f - __bfloat162float(h));
}
__device__ __forceinline__ unsigned pack2(__nv_bfloat16 a, __nv_bfloat16 b) {
    return (unsigned)__bfloat16_as_ushort(a) | ((unsigned)__bfloat16_as_ushort(b) << 16);
}
__device__ __forceinline__ void mma_bf16(float* c, const unsigned* a, unsigned b0, unsigned b1) {
    asm volatile(
        "mma.sync.aligned.m16n8k16.row.col.f32.bf16.bf16.f32 "
        "{%0,%1,%2,%3},{%4,%5,%6,%7},{%8,%9},{%0,%1,%2,%3};"
        : "+f"(c[0]), "+f"(c[1]), "+f"(c[2]), "+f"(c[3])
        : "r"(a[0]), "r"(a[1]), "r"(a[2]), "r"(a[3]), "r"(b0), "r"(b1));
}

// ============================================================================
// Weight pre-split: w [K][N] fp32 -> [Npad][Kpad2] packed k-pair words.
// word(n,p) = pack(bf16(w[2p][n]) lo-half, bf16(w[2p+1][n]) hi-half).
// ============================================================================
__global__ __launch_bounds__(256)
void convw_kernel(const float* __restrict__ src, uint32_t* __restrict__ dh,
                  uint32_t* __restrict__ dl, int K, int N, int Kpad2, int Npad)
{
    int idx = blockIdx.x * 256 + threadIdx.x;
    if (idx >= Npad * Kpad2) return;
    int n = idx / Kpad2, p = idx - n * Kpad2;
    int k0 = 2 * p, k1 = 2 * p + 1;
    float v0 = (k0 < K && n < N) ? src[(size_t)k0 * N + n] : 0.f;
    float v1 = (k1 < K && n < N) ? src[(size_t)k1 * N + n] : 0.f;
    __nv_bfloat16 h0, l0, h1, l1;
    splitf(v0, h0, l0); splitf(v1, h1, l1);
    dh[idx] = pack2(h0, h1);
    dl[idx] = pack2(l0, l1);
}

// label_emb [NROWS][47] -> [MPAD][32 words] bf16 hi/lo k-pair packed, zero padded
__global__ __launch_bounds__(256)
void convl_kernel(const float* __restrict__ emb, uint32_t* __restrict__ dh,
                  uint32_t* __restrict__ dl)
{
    int idx = blockIdx.x * 256 + threadIdx.x;
    if (idx >= MPAD * 32) return;
    int r = idx >> 5, p = idx & 31;
    int k0 = 2 * p, k1 = 2 * p + 1;
    float v0 = (r < NROWS && k0 < C_) ? emb[(size_t)r * C_ + k0] : 0.f;
    float v1 = (r < NROWS && k1 < C_) ? emb[(size_t)r * C_ + k1] : 0.f;
    __nv_bfloat16 h0, l0, h1, l1;
    splitf(v0, h0, l0); splitf(v1, h1, l1);
    dh[idx] = pack2(h0, h1);
    dl[idx] = pack2(l0, l1);
}

// ============================================================================
// Fused recursive attention: one warp per row; emits right packed hi/lo words.
// Lane owns feature pair (2*lane+64j, 2*lane+64j+1) -> one packed word each.
// ============================================================================
__global__ __launch_bounds__(256)
void att_kernel(const float* __restrict__ feat, const float* __restrict__ wa,
                const float* __restrict__ ba_p,
                uint32_t* __restrict__ rhi, uint32_t* __restrict__ rlo)
{
    const int gw   = (blockIdx.x * blockDim.x + threadIdx.x) >> 5;
    const int lane = threadIdx.x & 31;
    if (gw >= MPAD) return;

    if (gw >= NROWS) {
#pragma unroll
        for (int j = 0; j < 4; j++) {
            rhi[(size_t)gw * 128 + lane + 32 * j] = 0u;
            rlo[(size_t)gw * 128 + lane + 32 * j] = 0u;
        }
        return;
    }

    const float ba = __ldg(ba_p);

    // lane owns elements e = 2*lane + 64*j and e+1  (j = 0..3)
    float wlv[8], wrv[8];
#pragma unroll
    for (int j = 0; j < 4; j++) {
        wlv[2*j]   = __ldg(wa + 2 * lane + 64 * j);
        wlv[2*j+1] = __ldg(wa + 2 * lane + 64 * j + 1);
        wrv[2*j]   = __ldg(wa + F_ + 2 * lane + 64 * j);
        wrv[2*j+1] = __ldg(wa + F_ + 2 * lane + 64 * j + 1);
    }

    float v[H_][8];
    const float* base = feat + (size_t)gw * F_;
#pragma unroll
    for (int h = 0; h < H_; h++) {
        const float* p = base + (size_t)h * NROWS * F_;
#pragma unroll
        for (int j = 0; j < 4; j++) {
            float2 f2 = *(const float2*)(p + 2 * lane + 64 * j);
            v[h][2*j] = f2.x; v[h][2*j+1] = f2.y;
        }
    }

    float xl[H_], xr[H_];
#pragma unroll
    for (int h = 0; h < H_; h++) {
        float sl = 0.f, sr = 0.f;
#pragma unroll
        for (int j = 0; j < 8; j++) { sl = fmaf(v[h][j], wlv[j], sl); sr = fmaf(v[h][j], wrv[j], sr); }
#pragma unroll
        for (int o = 16; o; o >>= 1) {
            sl += __shfl_xor_sync(0xffffffffu, sl, o);
            sr += __shfl_xor_sync(0xffffffffu, sr, o);
        }
        xl[h] = sl; xr[h] = sr;
    }

    float s[H_];
    { float t = xl[0] + xr[0] + ba; s[0] = t >= 0.f ? t : 0.2f * t; }
#pragma unroll
    for (int i = 1; i < H_; i++) {
        float m = s[0];
        for (int h2 = 1; h2 < i; h2++) m = fmaxf(m, s[h2]);
        float den = 0.f, num = 0.f;
        for (int h2 = 0; h2 < i; h2++) {
            float e = __expf(s[h2] - m);
            den += e; num = fmaf(e, xl[h2], num);
        }
        float t = num / den + xr[i] + ba;
        s[i] = t >= 0.f ? t : 0.2f * t;
    }

    float m = s[0];
#pragma unroll
    for (int h2 = 1; h2 < H_; h2++) m = fmaxf(m, s[h2]);
    float e[H_], den = 0.f;
#pragma unroll
    for (int h2 = 0; h2 < H_; h2++) { e[h2] = __expf(s[h2] - m); den += e[h2]; }
    const float inv = 1.f / den;

#pragma unroll
    for (int j = 0; j < 4; j++) {
        float a0 = 0.f, a1 = 0.f;
#pragma unroll
        for (int h2 = 0; h2 < H_; h2++) {
            float w = e[h2] * inv;
            a0 = fmaf(w, v[h2][2*j], a0);
            a1 = fmaf(w, v[h2][2*j+1], a1);
        }
        __nv_bfloat16 h0, l0, h1, l1;
        splitf(a0, h0, l0); splitf(a1, h1, l1);
        rhi[(size_t)gw * 128 + lane + 32 * j] = pack2(h0, h1);
        rlo[(size_t)gw * 128 + lane + 32 * j] = pack2(l0, l1);
    }
}

// ============================================================================
// bf16x3 GEMM, 512 threads (16 warps, 4x4), tile 128x128, BK=32, double-
// buffered. A and B both [rows][kpair-words]; staging = 1 LDG.128 + 1 STS.128
// per component per thread per tile. No guards (all dims padded).
// Epilogues (fp32 math):
//  1: y=prelu(v+bias,a)                    -> Yhi/Ylo
//  2: out[r,c]=v+bias[c]                   (mask r<NROWS,c<47)
//  3: t=v+bias; Xout=t; y=0.5*(prelu(t)+t) -> Yhi/Ylo
//  4: t=v+prelu(Xin); xi=prelu(t); Xout=xi; y=0.5*(xi+Xin) -> Yhi/Ylo
//  5: t=v+Xin; y=prelu(t)                  -> Yhi/Ylo
//  6: out[r,c]+=v+bias[c]                  (mask)
// ============================================================================
template<int EPI>
__global__ __launch_bounds__(512)
void gemm512(const uint32_t* __restrict__ Ahi, const uint32_t* __restrict__ Alo, int ApW,
             const uint32_t* __restrict__ Bph, const uint32_t* __restrict__ Bpl, int Kp2,
             int ktiles,
             const float* __restrict__ bias, const float* __restrict__ Xin,
             float* __restrict__ Xout,
             uint32_t* __restrict__ Yhi, uint32_t* __restrict__ Ylo,
             float* __restrict__ outp, const float* __restrict__ alpha_p)
{
    extern __shared__ unsigned sh[];

    const int tid  = threadIdx.x;
    const int wid  = tid >> 5, lane = tid & 31;
    const int wr   = wid >> 2, wc = wid & 3;       // 4x4 warp grid
    const int g    = lane >> 2, t4 = lane & 3;
    const int rowBase = blockIdx.y * 128;
    const int colBase = blockIdx.x * 128;

    // staging mapping: row = tid>>2 (0..127), q = tid&3 (uint4 within 16-pair row)
    const int srow = tid >> 2, sq = tid & 3;
    const int aRowW = ApW >> 2;     // uint4 per A row
    const int bRowW = Kp2 >> 2;     // uint4 per B row

    const uint4* A4h = (const uint4*)Ahi;
    const uint4* A4l = (const uint4*)Alo;
    const uint4* B4h = (const uint4*)Bph;
    const uint4* B4l = (const uint4*)Bpl;

    float acc[2][4][4];
#pragma unroll
    for (int mi = 0; mi < 2; mi++)
#pragma unroll
        for (int ni = 0; ni < 4; ni++)
#pragma unroll
            for (int q = 0; q < 4; q++) acc[mi][ni][q] = 0.f;

    uint4 vAh, vAl, vBh, vBl;
    auto loadAB = [&](int kt) {
        size_t ai = (size_t)(rowBase + srow) * aRowW + kt * 4 + sq;
        size_t bi = (size_t)(colBase + srow) * bRowW + kt * 4 + sq;
        vAh = A4h[ai]; vAl = A4l[ai];
        vBh = B4h[bi]; vBl = B4l[bi];
    };
    auto stage = [&](int buf) {
        unsigned* base = sh + buf * BUFW;
        const int o = srow * 5 + sq;            // uint4 offset within component
        ((uint4*)(base          ))[o] = vAh;
        ((uint4*)(base + COMPW  ))[o] = vAl;
        ((uint4*)(base + 2*COMPW))[o] = vBh;
        ((uint4*)(base + 3*COMPW))[o] = vBl;
    };
    auto compute = [&](int buf) {
        const unsigned* aH = sh + buf * BUFW;
        const unsigned* aL = aH + COMPW;
        const unsigned* bH = aL + COMPW;
        const unsigned* bL = bH + COMPW;
#pragma unroll
        for (int kk = 0; kk < 2; kk++) {
            const int p0 = kk * 8 + t4;
            unsigned ah[2][4], al[2][4];
#pragma unroll
            for (int mi = 0; mi < 2; mi++) {
                int r = wr * 32 + mi * 16 + g;
                ah[mi][0] = aH[r * ASTR + p0];
                ah[mi][1] = aH[(r + 8) * ASTR + p0];
                ah[mi][2] = aH[r * ASTR + p0 + 4];
                ah[mi][3] = aH[(r + 8) * ASTR + p0 + 4];
                al[mi][0] = aL[r * ASTR + p0];
                al[mi][1] = aL[(r + 8) * ASTR + p0];
                al[mi][2] = aL[r * ASTR + p0 + 4];
                al[mi][3] = aL[(r + 8) * ASTR + p0 + 4];
            }
#pragma unroll
            for (int ni = 0; ni < 4; ni++) {
                int cb = wc * 32 + ni * 8 + g;
                unsigned bh0 = bH[cb * ASTR + p0];
                unsigned bh1 = bH[cb * ASTR + p0 + 4];
                unsigned bl0 = bL[cb * ASTR + p0];
                unsigned bl1 = bL[cb * ASTR + p0 + 4];
#pragma unroll
                for (int mi = 0; mi < 2; mi++) {
                    mma_bf16(acc[mi][ni], ah[mi], bh0, bh1);  // hi*hi
                    mma_bf16(acc[mi][ni], ah[mi], bl0, bl1);  // hi*lo
                    mma_bf16(acc[mi][ni], al[mi], bh0, bh1);  // lo*hi
                }
            }
        }
    };

    // ---- pipelined mainloop: one sync per K-tile ----
    loadAB(0);
    stage(0);
    __syncthreads();
    if (ktiles > 1) loadAB(1);

    for (int kt = 0; kt < ktiles; kt++) {
        compute(kt & 1);
        if (kt + 1 < ktiles) {
            stage((kt + 1) & 1);
            __syncthreads();
            if (kt + 2 < ktiles) loadAB(kt + 2);
        }
    }

    // ---- epilogue ----
    float alpha = 0.f;
    if (EPI == 1 || EPI == 3 || EPI == 4 || EPI == 5) alpha = __ldg(alpha_p);

#pragma unroll
    for (int mi = 0; mi < 2; mi++) {
#pragma unroll
        for (int ni = 0; ni < 4; ni++) {
            const int r0 = rowBase + wr * 32 + mi * 16 + g;
            const int c0 = colBase + wc * 32 + ni * 8 + 2 * t4;
            if (EPI == 2 || EPI == 6) {
#pragma unroll
                for (int q = 0; q < 4; q++) {
                    int r = r0 + (q >= 2 ? 8 : 0);
                    int c = c0 + (q & 1);
                    if (c < C_ && r < NROWS) {
                        float t = acc[mi][ni][q] + __ldg(bias + c);
                        size_t idx = (size_t)r * C_ + c;
                        if (EPI == 6) t += outp[idx];
                        outp[idx] = t;
                    }
                }
            } else {
#pragma unroll
                for (int half = 0; half < 2; half++) {
                    const int r = r0 + half * 8;
                    float v0 = acc[mi][ni][half * 2 + 0];
                    float v1 = acc[mi][ni][half * 2 + 1];
                    float y0, y1;
                    if (EPI == 1) {
                        float t0 = v0 + __ldg(bias + c0);
                        float t1 = v1 + __ldg(bias + c0 + 1);
                        y0 = t0 >= 0.f ? t0 : alpha * t0;
                        y1 = t1 >= 0.f ? t1 : alpha * t1;
                    } else if (EPI == 3) {
                        float t0 = v0 + __ldg(bias + c0);
                        float t1 = v1 + __ldg(bias + c0 + 1);
                        Xout[(size_t)r * HIDD + c0]     = t0;
                        Xout[(size_t)r * HIDD + c0 + 1] = t1;
                        float p0 = t0 >= 0.f ? t0 : alpha * t0;
                        float p1 = t1 >= 0.f ? t1 : alpha * t1;
                        y0 = 0.5f * (p0 + t0);
                        y1 = 0.5f * (p1 + t1);
                    } else if (EPI == 4) {
                        float xa = Xin[(size_t)r * HIDD + c0];
                        float xb = Xin[(size_t)r * HIDD + c0 + 1];
                        float pa = xa >= 0.f ? xa : alpha * xa;
                        float pb = xb >= 0.f ? xb : alpha * xb;
                        float t0 = v0 + pa, t1 = v1 + pb;
                        float p0 = t0 >= 0.f ? t0 : alpha * t0;
                        float p1 = t1 >= 0.f ? t1 : alpha * t1;
                        Xout[(size_t)r * HIDD + c0]     = p0;
                        Xout[(size_t)r * HIDD + c0 + 1] = p1;
                        y0 = 0.5f * (p0 + xa);
                        y1 = 0.5f * (p1 + xb);
                    } else { // EPI == 5
                        float t0 = v0 + Xin[(size_t)r * HIDD + c0];
                        float t1 = v1 + Xin[(size_t)r * HIDD + c0 + 1];
                        y0 = t0 >= 0.f ? t0 : alpha * t0;
                        y1 = t1 >= 0.f ? t1 : alpha * t1;
                    }
                    __nv_bfloat16 h0, l0, h1, l1;
                    splitf(y0, h0, l0);
                    splitf(y1, h1, l1);
                    Yhi[(size_t)r * HIDDW + (c0 >> 1)] = pack2(h0, h1);
                    Ylo[(size_t)r * HIDDW + (c0 >> 1)] = pack2(l0, l1);
                }
            }
        }
    }
}

// ============================================================================
extern "C" void kernel_launch(void* const* d_in, const int* in_sizes, int n_in,
                              void* d_out, int out_size)
{
    (void)in_sizes; (void)n_in; (void)out_size;

    const float* features  = (const float*)d_in[0];
    const float* label_emb = (const float*)d_in[1];
    const float* wa        = (const float*)d_in[2];
    const float* ba        = (const float*)d_in[3];
    const float* w0        = (const float*)d_in[4];
    const float* b0        = (const float*)d_in[5];
    const float* wg1       = (const float*)d_in[6];
    const float* wg2       = (const float*)d_in[7];
    const float* w_last    = (const float*)d_in[8];
    const float* b_last    = (const float*)d_in[9];
    const float* a_out     = (const float*)d_in[10];
    const float* wl0       = (const float*)d_in[11];
    const float* bl0       = (const float*)d_in[12];
    const float* wl1       = (const float*)d_in[13];
    const float* bl1       = (const float*)d_in[14];
    const float* wl2       = (const float*)d_in[15];
    const float* bl2       = (const float*)d_in[16];
    const float* wl3       = (const float*)d_in[17];
    const float* bl3       = (const float*)d_in[18];
    const float* a_lab     = (const float*)d_in[19];
    float* out = (float*)d_out;

    uint32_t *Wph, *Wpl, *L0h, *L0l, *Ah, *Al, *Bh, *Bl, *Rh, *Rl;
    float *X1, *X2;
    cudaGetSymbolAddress((void**)&Wph, g_Wph);
    cudaGetSymbolAddress((void**)&Wpl, g_Wpl);
    cudaGetSymbolAddress((void**)&L0h, g_L0h);
    cudaGetSymbolAddress((void**)&L0l, g_L0l);
    cudaGetSymbolAddress((void**)&Ah,  g_Ah);
    cudaGetSymbolAddress((void**)&Al,  g_Al);
    cudaGetSymbolAddress((void**)&Bh,  g_Bh);
    cudaGetSymbolAddress((void**)&Bl,  g_Bl);
    cudaGetSymbolAddress((void**)&Rh,  g_Rh);
    cudaGetSymbolAddress((void**)&Rl,  g_Rl);
    cudaGetSymbolAddress((void**)&X1,  g_X1);
    cudaGetSymbolAddress((void**)&X2,  g_X2);

    cudaFuncSetAttribute(gemm512<1>, cudaFuncAttributeMaxDynamicSharedMemorySize, SMEM_DYN);
    cudaFuncSetAttribute(gemm512<2>, cudaFuncAttributeMaxDynamicSharedMemorySize, SMEM_DYN);
    cudaFuncSetAttribute(gemm512<3>, cudaFuncAttributeMaxDynamicSharedMemorySize, SMEM_DYN);
    cudaFuncSetAttribute(gemm512<4>, cudaFuncAttributeMaxDynamicSharedMemorySize, SMEM_DYN);
    cudaFuncSetAttribute(gemm512<5>, cudaFuncAttributeMaxDynamicSharedMemorySize, SMEM_DYN);
    cudaFuncSetAttribute(gemm512<6>, cudaFuncAttributeMaxDynamicSharedMemorySize, SMEM_DYN);

    dim3 blk(256);
    auto cwg = [](size_t n) { return dim3((unsigned)((n + 255) / 256)); };

    // ---- weight pre-split: [K][N] fp32 -> [Npad][Kpad2] packed words ----
    convw_kernel<<<cwg(512 *  32), blk>>>(wl0,    Wph + O_wl0,   Wpl + O_wl0,   C_,   HIDD,  32, 512);
    convw_kernel<<<cwg(512 * 256), blk>>>(wl1,    Wph + O_wl1,   Wpl + O_wl1,   HIDD, HIDD, 256, 512);
    convw_kernel<<<cwg(512 * 256), blk>>>(wl2,    Wph + O_wl2,   Wpl + O_wl2,   HIDD, HIDD, 256, 512);
    convw_kernel<<<cwg(128 * 256), blk>>>(wl3,    Wph + O_wl3,   Wpl + O_wl3,   HIDD, C_,   256, 128);
    convw_kernel<<<cwg(512 * 128), blk>>>(w0,     Wph + O_w0,    Wpl + O_w0,    F_,   HIDD, 128, 512);
    convw_kernel<<<cwg(512 * 256), blk>>>(wg1,    Wph + O_wg1,   Wpl + O_wg1,   HIDD, HIDD, 256, 512);
    convw_kernel<<<cwg(512 * 256), blk>>>(wg2,    Wph + O_wg2,   Wpl + O_wg2,   HIDD, HIDD, 256, 512);
    convw_kernel<<<cwg(128 * 256), blk>>>(w_last, Wph + O_wlast, Wpl + O_wlast, HIDD, C_,   256, 128);
    convl_kernel<<<cwg((size_t)MPAD * 32), blk>>>(label_emb, L0h, L0l);

    // ---- attention -> right (packed hi/lo words) ----
    att_kernel<<<dim3(MPAD / 8), blk>>>(features, wa, ba, Rh, Rl);

    dim3 tblk(512);
    dim3 g512(4, MPAD / 128);
    dim3 g47(1, MPAD / 128);

    // ---- label branch ----
    gemm512<1><<<g512, tblk, SMEM_DYN>>>(L0h, L0l, 32,  Wph + O_wl0, Wpl + O_wl0, 32,  2,
                                         bl0, nullptr, nullptr, Ah, Al, nullptr, a_lab);
    gemm512<1><<<g512, tblk, SMEM_DYN>>>(Ah, Al, 256, Wph + O_wl1, Wpl + O_wl1, 256, 16,
                                         bl1, nullptr, nullptr, Bh, Bl, nullptr, a_lab);
    gemm512<1><<<g512, tblk, SMEM_DYN>>>(Bh, Bl, 256, Wph + O_wl2, Wpl + O_wl2, 256, 16,
                                         bl2, nullptr, nullptr, Ah, Al, nullptr, a_lab);
    gemm512<2><<<g47,  tblk, SMEM_DYN>>>(Ah, Al, 256, Wph + O_wl3, Wpl + O_wl3, 256, 16,
                                         bl3, nullptr, nullptr, nullptr, nullptr, out, nullptr);

    // ---- feature branch ----
    gemm512<3><<<g512, tblk, SMEM_DYN>>>(Rh, Rl, 128, Wph + O_w0, Wpl + O_w0, 128, 8,
                                         b0, nullptr, X1, Bh, Bl, nullptr, a_out);
    gemm512<4><<<g512, tblk, SMEM_DYN>>>(Bh, Bl, 256, Wph + O_wg1, Wpl + O_wg1, 256, 16,
                                         nullptr, X1, X2, Ah, Al, nullptr, a_out);
    gemm512<5><<<g512, tblk, SMEM_DYN>>>(Ah, Al, 256, Wph + O_wg2, Wpl + O_wg2, 256, 16,
                                         nullptr, X2, nullptr, Bh, Bl, nullptr, a_out);
    gemm512<6><<<g47,  tblk, SMEM_DYN>>>(Bh, Bl, 256, Wph + O_wlast, Wpl + O_wlast, 256, 16,
                                         b_last, nullptr, nullptr, nullptr, nullptr, out, a_out);
}

// round 11
// speedup vs baseline: 2.2534x; 1.0225x over previous
#include <cuda_runtime.h>
#include <cuda_bf16.h>
#include <cstdint>

// ---------------- problem constants ----------------
namespace {
constexpr int H_    = 10;
constexpr int NROWS = 100000;
constexpr int MPAD  = 100096;            // 782 * 128
constexpr int F_    = 256;
constexpr int HIDD  = 512;
constexpr int C_    = 47;
constexpr int HIDDW = HIDD / 2;          // 256 words per activation row

constexpr int ASTR  = 20;                // smem row stride in words (16 pairs + pad)
constexpr int COMPW = 128 * ASTR;        // 2560 words per component
constexpr int BUFW  = 4 * COMPW;         // Ahi,Alo,Bhi,Blo = 10240 words
constexpr int SMEM_DYN = 2 * BUFW * 4;   // 81920 B double-buffered

// packed-weight offsets in WORDS, layout [Npad][Kpad2] (n-major rows of k-pair words)
constexpr size_t O_wl0   = 0;            // 512 x 32  = 16384
constexpr size_t O_wl1   = 16384;        // 512 x 256 = 131072
constexpr size_t O_wl2   = 147456;       // 131072
constexpr size_t O_wl3   = 278528;       // 128 x 256 = 32768
constexpr size_t O_w0    = 311296;       // 512 x 128 = 65536
constexpr size_t O_wg1   = 376832;       // 131072
constexpr size_t O_wg2   = 507904;       // 131072
constexpr size_t O_wlast = 638976;       // 32768
constexpr size_t W_WORDS = 671744;
}

// ---------------- device scratch (word-typed => alignment guaranteed) ----
__device__ uint32_t g_Wph[W_WORDS];
__device__ uint32_t g_Wpl[W_WORDS];
__device__ uint32_t g_L0h[(size_t)MPAD * 32];
__device__ uint32_t g_L0l[(size_t)MPAD * 32];
__device__ uint32_t g_Ah[(size_t)MPAD * HIDDW];
__device__ uint32_t g_Al[(size_t)MPAD * HIDDW];
__device__ uint32_t g_Bh[(size_t)MPAD * HIDDW];
__device__ uint32_t g_Bl[(size_t)MPAD * HIDDW];
__device__ uint32_t g_Rh[(size_t)MPAD * 128];
__device__ uint32_t g_Rl[(size_t)MPAD * 128];
__device__ float g_X1[(size_t)MPAD * HIDD];
__device__ float g_X2[(size_t)MPAD * HIDD];

// ---------------- helpers ----------------
__device__ __forceinline__ void splitf(float f, __nv_bfloat16& h, __nv_bfloat16& l) {
    h = __float2bfloat16(f);
    l = __float2bfloat16(f - __bfloat162float(h));
}
__device__ __forceinline__ unsigned pack2(__nv_bfloat16 a, __nv_bfloat16 b) {
    return (unsigned)__bfloat16_as_ushort(a) | ((unsigned)__bfloat16_as_ushort(b) << 16);
}
__device__ __forceinline__ void mma_bf16(float* c, const unsigned* a, unsigned b0, unsigned b1) {
    asm volatile(
        "mma.sync.aligned.m16n8k16.row.col.f32.bf16.bf16.f32 "
        "{%0,%1,%2,%3},{%4,%5,%6,%7},{%8,%9},{%0,%1,%2,%3};"
        : "+f"(c[0]), "+f"(c[1]), "+f"(c[2]), "+f"(c[3])
        : "r"(a[0]), "r"(a[1]), "r"(a[2]), "r"(a[3]), "r"(b0), "r"(b1));
}
__device__ __forceinline__ uint32_t smem_u32(const void* p) {
    uint32_t a;
    asm("{ .reg .u64 t; cvta.to.shared.u64 t, %1; cvt.u32.u64 %0, t; }" : "=r"(a) : "l"(p));
    return a;
}
#define LDSM4(r0, r1, r2, r3, addr) \
    asm volatile("ldmatrix.sync.aligned.m8n8.x4.shared.b16 {%0,%1,%2,%3}, [%4];" \
        : "=r"(r0), "=r"(r1), "=r"(r2), "=r"(r3) : "r"(addr))

// ============================================================================
// Weight pre-split: w [K][N] fp32 -> [Npad][Kpad2] packed k-pair words.
// ============================================================================
__global__ __launch_bounds__(256)
void convw_kernel(const float* __restrict__ src, uint32_t* __restrict__ dh,
                  uint32_t* __restrict__ dl, int K, int N, int Kpad2, int Npad)
{
    int idx = blockIdx.x * 256 + threadIdx.x;
    if (idx >= Npad * Kpad2) return;
    int n = idx / Kpad2, p = idx - n * Kpad2;
    int k0 = 2 * p, k1 = 2 * p + 1;
    float v0 = (k0 < K && n < N) ? src[(size_t)k0 * N + n] : 0.f;
    float v1 = (k1 < K && n < N) ? src[(size_t)k1 * N + n] : 0.f;
    __nv_bfloat16 h0, l0, h1, l1;
    splitf(v0, h0, l0); splitf(v1, h1, l1);
    dh[idx] = pack2(h0, h1);
    dl[idx] = pack2(l0, l1);
}

// label_emb [NROWS][47] -> [MPAD][32 words] bf16 hi/lo k-pair packed
__global__ __launch_bounds__(256)
void convl_kernel(const float* __restrict__ emb, uint32_t* __restrict__ dh,
                  uint32_t* __restrict__ dl)
{
    int idx = blockIdx.x * 256 + threadIdx.x;
    if (idx >= MPAD * 32) return;
    int r = idx >> 5, p = idx & 31;
    int k0 = 2 * p, k1 = 2 * p + 1;
    float v0 = (r < NROWS && k0 < C_) ? emb[(size_t)r * C_ + k0] : 0.f;
    float v1 = (r < NROWS && k1 < C_) ? emb[(size_t)r * C_ + k1] : 0.f;
    __nv_bfloat16 h0, l0, h1, l1;
    splitf(v0, h0, l0); splitf(v1, h1, l1);
    dh[idx] = pack2(h0, h1);
    dl[idx] = pack2(l0, l1);
}

// ============================================================================
// Fused recursive attention: one warp per row; emits right packed hi/lo words.
// ============================================================================
__global__ __launch_bounds__(256)
void att_kernel(const float* __restrict__ feat, const float* __restrict__ wa,
                const float* __restrict__ ba_p,
                uint32_t* __restrict__ rhi, uint32_t* __restrict__ rlo)
{
    const int gw   = (blockIdx.x * blockDim.x + threadIdx.x) >> 5;
    const int lane = threadIdx.x & 31;
    if (gw >= MPAD) return;

    if (gw >= NROWS) {
#pragma unroll
        for (int j = 0; j < 4; j++) {
            rhi[(size_t)gw * 128 + lane + 32 * j] = 0u;
            rlo[(size_t)gw * 128 + lane + 32 * j] = 0u;
        }
        return;
    }

    const float ba = __ldg(ba_p);

    float wlv[8], wrv[8];
#pragma unroll
    for (int j = 0; j < 4; j++) {
        wlv[2*j]   = __ldg(wa + 2 * lane + 64 * j);
        wlv[2*j+1] = __ldg(wa + 2 * lane + 64 * j + 1);
        wrv[2*j]   = __ldg(wa + F_ + 2 * lane + 64 * j);
        wrv[2*j+1] = __ldg(wa + F_ + 2 * lane + 64 * j + 1);
    }

    float v[H_][8];
    const float* base = feat + (size_t)gw * F_;
#pragma unroll
    for (int h = 0; h < H_; h++) {
        const float* p = base + (size_t)h * NROWS * F_;
#pragma unroll
        for (int j = 0; j < 4; j++) {
            float2 f2 = *(const float2*)(p + 2 * lane + 64 * j);
            v[h][2*j] = f2.x; v[h][2*j+1] = f2.y;
        }
    }

    float xl[H_], xr[H_];
#pragma unroll
    for (int h = 0; h < H_; h++) {
        float sl = 0.f, sr = 0.f;
#pragma unroll
        for (int j = 0; j < 8; j++) { sl = fmaf(v[h][j], wlv[j], sl); sr = fmaf(v[h][j], wrv[j], sr); }
#pragma unroll
        for (int o = 16; o; o >>= 1) {
            sl += __shfl_xor_sync(0xffffffffu, sl, o);
            sr += __shfl_xor_sync(0xffffffffu, sr, o);
        }
        xl[h] = sl; xr[h] = sr;
    }

    float s[H_];
    { float t = xl[0] + xr[0] + ba; s[0] = t >= 0.f ? t : 0.2f * t; }
#pragma unroll
    for (int i = 1; i < H_; i++) {
        float m = s[0];
        for (int h2 = 1; h2 < i; h2++) m = fmaxf(m, s[h2]);
        float den = 0.f, num = 0.f;
        for (int h2 = 0; h2 < i; h2++) {
            float e = __expf(s[h2] - m);
            den += e; num = fmaf(e, xl[h2], num);
        }
        float t = num / den + xr[i] + ba;
        s[i] = t >= 0.f ? t : 0.2f * t;
    }

    float m = s[0];
#pragma unroll
    for (int h2 = 1; h2 < H_; h2++) m = fmaxf(m, s[h2]);
    float e[H_], den = 0.f;
#pragma unroll
    for (int h2 = 0; h2 < H_; h2++) { e[h2] = __expf(s[h2] - m); den += e[h2]; }
    const float inv = 1.f / den;

#pragma unroll
    for (int j = 0; j < 4; j++) {
        float a0 = 0.f, a1 = 0.f;
#pragma unroll
        for (int h2 = 0; h2 < H_; h2++) {
            float w = e[h2] * inv;
            a0 = fmaf(w, v[h2][2*j], a0);
            a1 = fmaf(w, v[h2][2*j+1], a1);
        }
        __nv_bfloat16 h0, l0, h1, l1;
        splitf(a0, h0, l0); splitf(a1, h1, l1);
        rhi[(size_t)gw * 128 + lane + 32 * j] = pack2(h0, h1);
        rlo[(size_t)gw * 128 + lane + 32 * j] = pack2(l0, l1);
    }
}

// ============================================================================
// bf16x3 GEMM, 512 threads (16 warps, 4x4), tile 128x128, BK=32, double-
// buffered, ldmatrix fragment loads (16 LDSM/tile/warp replaces 64 LDS.32).
// ============================================================================
template<int EPI>
__global__ __launch_bounds__(512)
void gemm512(const uint32_t* __restrict__ Ahi, const uint32_t* __restrict__ Alo, int ApW,
             const uint32_t* __restrict__ Bph, const uint32_t* __restrict__ Bpl, int Kp2,
             int ktiles,
             const float* __restrict__ bias, const float* __restrict__ Xin,
             float* __restrict__ Xout,
             uint32_t* __restrict__ Yhi, uint32_t* __restrict__ Ylo,
             float* __restrict__ outp, const float* __restrict__ alpha_p)
{
    extern __shared__ unsigned sh[];

    const int tid  = threadIdx.x;
    const int wid  = tid >> 5, lane = tid & 31;
    const int wr   = wid >> 2, wc = wid & 3;       // 4x4 warp grid
    const int g    = lane >> 2, t4 = lane & 3;
    const int rowBase = blockIdx.y * 128;
    const int colBase = blockIdx.x * 128;

    const uint32_t smem_base = smem_u32(sh);

    // ldmatrix lane roles: lm = matrix id (0..3), lr = row within matrix
    const int lm = lane >> 3, lr = lane & 7;
    int aIdx[2];
#pragma unroll
    for (int mi = 0; mi < 2; mi++)
        aIdx[mi] = (wr * 32 + mi * 16 + (lm & 1) * 8 + lr) * ASTR + (lm >> 1) * 4;
    const int bIdx = (wc * 32 + lm * 8 + lr) * ASTR;

    const int srow = tid >> 2, sq = tid & 3;
    const int aRowW = ApW >> 2;
    const int bRowW = Kp2 >> 2;

    const uint4* A4h = (const uint4*)Ahi;
    const uint4* A4l = (const uint4*)Alo;
    const uint4* B4h = (const uint4*)Bph;
    const uint4* B4l = (const uint4*)Bpl;

    float acc[2][4][4];
#pragma unroll
    for (int mi = 0; mi < 2; mi++)
#pragma unroll
        for (int ni = 0; ni < 4; ni++)
#pragma unroll
            for (int q = 0; q < 4; q++) acc[mi][ni][q] = 0.f;

    uint4 vAh, vAl, vBh, vBl;
    auto loadAB = [&](int kt) {
        size_t ai = (size_t)(rowBase + srow) * aRowW + kt * 4 + sq;
        size_t bi = (size_t)(colBase + srow) * bRowW + kt * 4 + sq;
        vAh = A4h[ai]; vAl = A4l[ai];
        vBh = B4h[bi]; vBl = B4l[bi];
    };
    auto stage = [&](int buf) {
        unsigned* base = sh + buf * BUFW;
        const int o = srow * 5 + sq;
        ((uint4*)(base          ))[o] = vAh;
        ((uint4*)(base + COMPW  ))[o] = vAl;
        ((uint4*)(base + 2*COMPW))[o] = vBh;
        ((uint4*)(base + 3*COMPW))[o] = vBl;
    };
    auto compute = [&](int buf) {
        const uint32_t bufo = smem_base + (uint32_t)buf * (BUFW * 4);
#pragma unroll
        for (int kk = 0; kk < 2; kk++) {
            const uint32_t koff = (uint32_t)(kk * 8 * 4);   // bytes
            unsigned ah[2][4], al[2][4];
#pragma unroll
            for (int mi = 0; mi < 2; mi++) {
                uint32_t aaddr = bufo + (uint32_t)(aIdx[mi] * 4) + koff;
                LDSM4(ah[mi][0], ah[mi][1], ah[mi][2], ah[mi][3], aaddr);
                LDSM4(al[mi][0], al[mi][1], al[mi][2], al[mi][3], aaddr + COMPW * 4);
            }
            unsigned bh0[4], bh1[4], bl0[4], bl1[4];
            {
                uint32_t baddr = bufo + (uint32_t)(2 * COMPW * 4) + (uint32_t)(bIdx * 4) + koff;
                LDSM4(bh0[0], bh0[1], bh0[2], bh0[3], baddr);
                LDSM4(bh1[0], bh1[1], bh1[2], bh1[3], baddr + 16);
                LDSM4(bl0[0], bl0[1], bl0[2], bl0[3], baddr + COMPW * 4);
                LDSM4(bl1[0], bl1[1], bl1[2], bl1[3], baddr + COMPW * 4 + 16);
            }
#pragma unroll
            for (int ni = 0; ni < 4; ni++) {
#pragma unroll
                for (int mi = 0; mi < 2; mi++) {
                    mma_bf16(acc[mi][ni], ah[mi], bh0[ni], bh1[ni]);  // hi*hi
                    mma_bf16(acc[mi][ni], ah[mi], bl0[ni], bl1[ni]);  // hi*lo
                    mma_bf16(acc[mi][ni], al[mi], bh0[ni], bh1[ni]);  // lo*hi
                }
            }
        }
    };

    // ---- pipelined mainloop: one sync per K-tile ----
    loadAB(0);
    stage(0);
    __syncthreads();
    if (ktiles > 1) loadAB(1);

    for (int kt = 0; kt < ktiles; kt++) {
        compute(kt & 1);
        if (kt + 1 < ktiles) {
            stage((kt + 1) & 1);
            __syncthreads();
            if (kt + 2 < ktiles) loadAB(kt + 2);
        }
    }

    // ---- epilogue ----
    float alpha = 0.f;
    if (EPI == 1 || EPI == 3 || EPI == 4 || EPI == 5) alpha = __ldg(alpha_p);

#pragma unroll
    for (int mi = 0; mi < 2; mi++) {
#pragma unroll
        for (int ni = 0; ni < 4; ni++) {
            const int r0 = rowBase + wr * 32 + mi * 16 + g;
            const int c0 = colBase + wc * 32 + ni * 8 + 2 * t4;
            if (EPI == 2 || EPI == 6) {
#pragma unroll
                for (int q = 0; q < 4; q++) {
                    int r = r0 + (q >= 2 ? 8 : 0);
                    int c = c0 + (q & 1);
                    if (c < C_ && r < NROWS) {
                        float t = acc[mi][ni][q] + __ldg(bias + c);
                        size_t idx = (size_t)r * C_ + c;
                        if (EPI == 6) t += outp[idx];
                        outp[idx] = t;
                    }
                }
            } else {
#pragma unroll
                for (int half = 0; half < 2; half++) {
                    const int r = r0 + half * 8;
                    float v0 = acc[mi][ni][half * 2 + 0];
                    float v1 = acc[mi][ni][half * 2 + 1];
                    float y0, y1;
                    if (EPI == 1) {
                        float t0 = v0 + __ldg(bias + c0);
                        float t1 = v1 + __ldg(bias + c0 + 1);
                        y0 = t0 >= 0.f ? t0 : alpha * t0;
                        y1 = t1 >= 0.f ? t1 : alpha * t1;
                    } else if (EPI == 3) {
                        float t0 = v0 + __ldg(bias + c0);
                        float t1 = v1 + __ldg(bias + c0 + 1);
                        Xout[(size_t)r * HIDD + c0]     = t0;
                        Xout[(size_t)r * HIDD + c0 + 1] = t1;
                        float p0 = t0 >= 0.f ? t0 : alpha * t0;
                        float p1 = t1 >= 0.f ? t1 : alpha * t1;
                        y0 = 0.5f * (p0 + t0);
                        y1 = 0.5f * (p1 + t1);
                    } else if (EPI == 4) {
                        float xa = Xin[(size_t)r * HIDD + c0];
                        float xb = Xin[(size_t)r * HIDD + c0 + 1];
                        float pa = xa >= 0.f ? xa : alpha * xa;
                        float pb = xb >= 0.f ? xb : alpha * xb;
                        float t0 = v0 + pa, t1 = v1 + pb;
                        float p0 = t0 >= 0.f ? t0 : alpha * t0;
                        float p1 = t1 >= 0.f ? t1 : alpha * t1;
                        Xout[(size_t)r * HIDD + c0]     = p0;
                        Xout[(size_t)r * HIDD + c0 + 1] = p1;
                        y0 = 0.5f * (p0 + xa);
                        y1 = 0.5f * (p1 + xb);
                    } else { // EPI == 5
                        float t0 = v0 + Xin[(size_t)r * HIDD + c0];
                        float t1 = v1 + Xin[(size_t)r * HIDD + c0 + 1];
                        y0 = t0 >= 0.f ? t0 : alpha * t0;
                        y1 = t1 >= 0.f ? t1 : alpha * t1;
                    }
                    __nv_bfloat16 h0, l0, h1, l1;
                    splitf(y0, h0, l0);
                    splitf(y1, h1, l1);
                    Yhi[(size_t)r * HIDDW + (c0 >> 1)] = pack2(h0, h1);
                    Ylo[(size_t)r * HIDDW + (c0 >> 1)] = pack2(l0, l1);
                }
            }
        }
    }
}

// ============================================================================
extern "C" void kernel_launch(void* const* d_in, const int* in_sizes, int n_in,
                              void* d_out, int out_size)
{
    (void)in_sizes; (void)n_in; (void)out_size;

    const float* features  = (const float*)d_in[0];
    const float* label_emb = (const float*)d_in[1];
    const float* wa        = (const float*)d_in[2];
    const float* ba        = (const float*)d_in[3];
    const float* w0        = (const float*)d_in[4];
    const float* b0        = (const float*)d_in[5];
    const float* wg1       = (const float*)d_in[6];
    const float* wg2       = (const float*)d_in[7];
    const float* w_last    = (const float*)d_in[8];
    const float* b_last    = (const float*)d_in[9];
    const float* a_out     = (const float*)d_in[10];
    const float* wl0       = (const float*)d_in[11];
    const float* bl0       = (const float*)d_in[12];
    const float* wl1       = (const float*)d_in[13];
    const float* bl1       = (const float*)d_in[14];
    const float* wl2       = (const float*)d_in[15];
    const float* bl2       = (const float*)d_in[16];
    const float* wl3       = (const float*)d_in[17];
    const float* bl3       = (const float*)d_in[18];
    const float* a_lab     = (const float*)d_in[19];
    float* out = (float*)d_out;

    uint32_t *Wph, *Wpl, *L0h, *L0l, *Ah, *Al, *Bh, *Bl, *Rh, *Rl;
    float *X1, *X2;
    cudaGetSymbolAddress((void**)&Wph, g_Wph);
    cudaGetSymbolAddress((void**)&Wpl, g_Wpl);
    cudaGetSymbolAddress((void**)&L0h, g_L0h);
    cudaGetSymbolAddress((void**)&L0l, g_L0l);
    cudaGetSymbolAddress((void**)&Ah,  g_Ah);
    cudaGetSymbolAddress((void**)&Al,  g_Al);
    cudaGetSymbolAddress((void**)&Bh,  g_Bh);
    cudaGetSymbolAddress((void**)&Bl,  g_Bl);
    cudaGetSymbolAddress((void**)&Rh,  g_Rh);
    cudaGetSymbolAddress((void**)&Rl,  g_Rl);
    cudaGetSymbolAddress((void**)&X1,  g_X1);
    cudaGetSymbolAddress((void**)&X2,  g_X2);

    cudaFuncSetAttribute(gemm512<1>, cudaFuncAttributeMaxDynamicSharedMemorySize, SMEM_DYN);
    cudaFuncSetAttribute(gemm512<2>, cudaFuncAttributeMaxDynamicSharedMemorySize, SMEM_DYN);
    cudaFuncSetAttribute(gemm512<3>, cudaFuncAttributeMaxDynamicSharedMemorySize, SMEM_DYN);
    cudaFuncSetAttribute(gemm512<4>, cudaFuncAttributeMaxDynamicSharedMemorySize, SMEM_DYN);
    cudaFuncSetAttribute(gemm512<5>, cudaFuncAttributeMaxDynamicSharedMemorySize, SMEM_DYN);
    cudaFuncSetAttribute(gemm512<6>, cudaFuncAttributeMaxDynamicSharedMemorySize, SMEM_DYN);

    dim3 blk(256);
    auto cwg = [](size_t n) { return dim3((unsigned)((n + 255) / 256)); };

    // ---- weight pre-split: [K][N] fp32 -> [Npad][Kpad2] packed words ----
    convw_kernel<<<cwg(512 *  32), blk>>>(wl0,    Wph + O_wl0,   Wpl + O_wl0,   C_,   HIDD,  32, 512);
    convw_kernel<<<cwg(512 * 256), blk>>>(wl1,    Wph + O_wl1,   Wpl + O_wl1,   HIDD, HIDD, 256, 512);
    convw_kernel<<<cwg(512 * 256), blk>>>(wl2,    Wph + O_wl2,   Wpl + O_wl2,   HIDD, HIDD, 256, 512);
    convw_kernel<<<cwg(128 * 256), blk>>>(wl3,    Wph + O_wl3,   Wpl + O_wl3,   HIDD, C_,   256, 128);
    convw_kernel<<<cwg(512 * 128), blk>>>(w0,     Wph + O_w0,    Wpl + O_w0,    F_,   HIDD, 128, 512);
    convw_kernel<<<cwg(512 * 256), blk>>>(wg1,    Wph + O_wg1,   Wpl + O_wg1,   HIDD, HIDD, 256, 512);
    convw_kernel<<<cwg(512 * 256), blk>>>(wg2,    Wph + O_wg2,   Wpl + O_wg2,   HIDD, HIDD, 256, 512);
    convw_kernel<<<cwg(128 * 256), blk>>>(w_last, Wph + O_wlast, Wpl + O_wlast, HIDD, C_,   256, 128);
    convl_kernel<<<cwg((size_t)MPAD * 32), blk>>>(label_emb, L0h, L0l);

    // ---- attention -> right (packed hi/lo words) ----
    att_kernel<<<dim3(MPAD / 8), blk>>>(features, wa, ba, Rh, Rl);

    dim3 tblk(512);
    dim3 g512(4, MPAD / 128);
    dim3 g47(1, MPAD / 128);

    // ---- label branch ----
    gemm512<1><<<g512, tblk, SMEM_DYN>>>(L0h, L0l, 32,  Wph + O_wl0, Wpl + O_wl0, 32,  2,
                                         bl0, nullptr, nullptr, Ah, Al, nullptr, a_lab);
    gemm512<1><<<g512, tblk, SMEM_DYN>>>(Ah, Al, 256, Wph + O_wl1, Wpl + O_wl1, 256, 16,
                                         bl1, nullptr, nullptr, Bh, Bl, nullptr, a_lab);
    gemm512<1><<<g512, tblk, SMEM_DYN>>>(Bh, Bl, 256, Wph + O_wl2, Wpl + O_wl2, 256, 16,
                                         bl2, nullptr, nullptr, Ah, Al, nullptr, a_lab);
    gemm512<2><<<g47,  tblk, SMEM_DYN>>>(Ah, Al, 256, Wph + O_wl3, Wpl + O_wl3, 256, 16,
                                         bl3, nullptr, nullptr, nullptr, nullptr, out, nullptr);

    // ---- feature branch ----
    gemm512<3><<<g512, tblk, SMEM_DYN>>>(Rh, Rl, 128, Wph + O_w0, Wpl + O_w0, 128, 8,
                                         b0, nullptr, X1, Bh, Bl, nullptr, a_out);
    gemm512<4><<<g512, tblk, SMEM_DYN>>>(Bh, Bl, 256, Wph + O_wg1, Wpl + O_wg1, 256, 16,
                                         nullptr, X1, X2, Ah, Al, nullptr, a_out);
    gemm512<5><<<g512, tblk, SMEM_DYN>>>(Ah, Al, 256, Wph + O_wg2, Wpl + O_wg2, 256, 16,
                                         nullptr, X2, nullptr, Bh, Bl, nullptr, a_out);
    gemm512<6><<<g47,  tblk, SMEM_DYN>>>(Bh, Bl, 256, Wph + O_wlast, Wpl + O_wlast, 256, 16,
                                         b_last, nullptr, nullptr, nullptr, nullptr, out, a_out);
}

// round 15
// speedup vs baseline: 2.2660x; 1.0056x over previous
#include <cuda_runtime.h>
#include <cuda_bf16.h>
#include <cstdint>

// ---------------- problem constants ----------------
namespace {
constexpr int H_    = 10;
constexpr int NROWS = 100000;
constexpr int MPAD  = 100096;            // 782 * 128
constexpr int F_    = 256;
constexpr int HIDD  = 512;
constexpr int C_    = 47;
constexpr int HIDDW = HIDD / 2;          // 256 words per activation row

constexpr int ASTR  = 20;                // smem row stride in words (16 pairs + pad)
constexpr int COMPW = 128 * ASTR;        // 2560 words per component
constexpr int BUFW  = 4 * COMPW;         // Ahi,Alo,Bhi,Blo = 10240 words
constexpr int SMEM_DYN = 2 * BUFW * 4;   // 81920 B double-buffered

// packed-weight offsets in WORDS, layout [Npad][Kpad2] (n-major rows of k-pair words)
constexpr size_t O_wl0   = 0;            // 512 x 32  = 16384
constexpr size_t O_wl1   = 16384;        // 512 x 256 = 131072
constexpr size_t O_wl2   = 147456;       // 131072
constexpr size_t O_wl3   = 278528;       // 128 x 256 = 32768
constexpr size_t O_w0    = 311296;       // 512 x 128 = 65536
constexpr size_t O_wg1   = 376832;       // 131072
constexpr size_t O_wg2   = 507904;       // 131072
constexpr size_t O_wlast = 638976;       // 32768
constexpr size_t W_WORDS = 671744;
}

// ---------------- device scratch (word-typed => alignment guaranteed) ----
__device__ uint32_t g_Wph[W_WORDS];
__device__ uint32_t g_Wpl[W_WORDS];
__device__ uint32_t g_L0h[(size_t)MPAD * 32];
__device__ uint32_t g_L0l[(size_t)MPAD * 32];
__device__ uint32_t g_Ah[(size_t)MPAD * HIDDW];
__device__ uint32_t g_Al[(size_t)MPAD * HIDDW];
__device__ uint32_t g_Bh[(size_t)MPAD * HIDDW];
__device__ uint32_t g_Bl[(size_t)MPAD * HIDDW];
__device__ uint32_t g_Rh[(size_t)MPAD * 128];
__device__ uint32_t g_Rl[(size_t)MPAD * 128];
__device__ float g_X1[(size_t)MPAD * HIDD];
__device__ float g_X2[(size_t)MPAD * HIDD];

// ---------------- helpers ----------------
__device__ __forceinline__ void splitf(float f, __nv_bfloat16& h, __nv_bfloat16& l) {
    h = __float2bfloat16(f);
    l = __float2bfloat16(f - __bfloat162float(h));
}
__device__ __forceinline__ unsigned pack2(__nv_bfloat16 a, __nv_bfloat16 b) {
    return (unsigned)__bfloat16_as_ushort(a) | ((unsigned)__bfloat16_as_ushort(b) << 16);
}
__device__ __forceinline__ void mma_bf16(float* c, const unsigned* a, unsigned b0, unsigned b1) {
    asm volatile(
        "mma.sync.aligned.m16n8k16.row.col.f32.bf16.bf16.f32 "
        "{%0,%1,%2,%3},{%4,%5,%6,%7},{%8,%9},{%0,%1,%2,%3};"
        : "+f"(c[0]), "+f"(c[1]), "+f"(c[2]), "+f"(c[3])
        : "r"(a[0]), "r"(a[1]), "r"(a[2]), "r"(a[3]), "r"(b0), "r"(b1));
}
__device__ __forceinline__ uint32_t smem_u32(const void* p) {
    uint32_t a;
    asm("{ .reg .u64 t; cvta.to.shared.u64 t, %1; cvt.u32.u64 %0, t; }" : "=r"(a) : "l"(p));
    return a;
}
#define LDSM4(r0, r1, r2, r3, addr) \
    asm volatile("ldmatrix.sync.aligned.m8n8.x4.shared.b16 {%0,%1,%2,%3}, [%4];" \
        : "=r"(r0), "=r"(r1), "=r"(r2), "=r"(r3) : "r"(addr))

// ============================================================================
// Weight pre-split: w [K][N] fp32 -> [Npad][Kpad2] packed k-pair words.
// ============================================================================
__global__ __launch_bounds__(256)
void convw_kernel(const float* __restrict__ src, uint32_t* __restrict__ dh,
                  uint32_t* __restrict__ dl, int K, int N, int Kpad2, int Npad)
{
    int idx = blockIdx.x * 256 + threadIdx.x;
    if (idx >= Npad * Kpad2) return;
    int n = idx / Kpad2, p = idx - n * Kpad2;
    int k0 = 2 * p, k1 = 2 * p + 1;
    float v0 = (k0 < K && n < N) ? src[(size_t)k0 * N + n] : 0.f;
    float v1 = (k1 < K && n < N) ? src[(size_t)k1 * N + n] : 0.f;
    __nv_bfloat16 h0, l0, h1, l1;
    splitf(v0, h0, l0); splitf(v1, h1, l1);
    dh[idx] = pack2(h0, h1);
    dl[idx] = pack2(l0, l1);
}

// label_emb [NROWS][47] -> [MPAD][32 words] bf16 hi/lo k-pair packed
__global__ __launch_bounds__(256)
void convl_kernel(const float* __restrict__ emb, uint32_t* __restrict__ dh,
                  uint32_t* __restrict__ dl)
{
    int idx = blockIdx.x * 256 + threadIdx.x;
    if (idx >= MPAD * 32) return;
    int r = idx >> 5, p = idx & 31;
    int k0 = 2 * p, k1 = 2 * p + 1;
    float v0 = (r < NROWS && k0 < C_) ? emb[(size_t)r * C_ + k0] : 0.f;
    float v1 = (r < NROWS && k1 < C_) ? emb[(size_t)r * C_ + k1] : 0.f;
    __nv_bfloat16 h0, l0, h1, l1;
    splitf(v0, h0, l0); splitf(v1, h1, l1);
    dh[idx] = pack2(h0, h1);
    dl[idx] = pack2(l0, l1);
}

// ============================================================================
// Fused recursive attention: one warp per row; emits right packed hi/lo words.
// ============================================================================
__global__ __launch_bounds__(256)
void att_kernel(const float* __restrict__ feat, const float* __restrict__ wa,
                const float* __restrict__ ba_p,
                uint32_t* __restrict__ rhi, uint32_t* __restrict__ rlo)
{
    const int gw   = (blockIdx.x * blockDim.x + threadIdx.x) >> 5;
    const int lane = threadIdx.x & 31;
    if (gw >= MPAD) return;

    if (gw >= NROWS) {
#pragma unroll
        for (int j = 0; j < 4; j++) {
            rhi[(size_t)gw * 128 + lane + 32 * j] = 0u;
            rlo[(size_t)gw * 128 + lane + 32 * j] = 0u;
        }
        return;
    }

    const float ba = __ldg(ba_p);

    float wlv[8], wrv[8];
#pragma unroll
    for (int j = 0; j < 4; j++) {
        wlv[2*j]   = __ldg(wa + 2 * lane + 64 * j);
        wlv[2*j+1] = __ldg(wa + 2 * lane + 64 * j + 1);
        wrv[2*j]   = __ldg(wa + F_ + 2 * lane + 64 * j);
        wrv[2*j+1] = __ldg(wa + F_ + 2 * lane + 64 * j + 1);
    }

    float v[H_][8];
    const float* base = feat + (size_t)gw * F_;
#pragma unroll
    for (int h = 0; h < H_; h++) {
        const float* p = base + (size_t)h * NROWS * F_;
#pragma unroll
        for (int j = 0; j < 4; j++) {
            float2 f2 = *(const float2*)(p + 2 * lane + 64 * j);
            v[h][2*j] = f2.x; v[h][2*j+1] = f2.y;
        }
    }

    float xl[H_], xr[H_];
#pragma unroll
    for (int h = 0; h < H_; h++) {
        float sl = 0.f, sr = 0.f;
#pragma unroll
        for (int j = 0; j < 8; j++) { sl = fmaf(v[h][j], wlv[j], sl); sr = fmaf(v[h][j], wrv[j], sr); }
#pragma unroll
        for (int o = 16; o; o >>= 1) {
            sl += __shfl_xor_sync(0xffffffffu, sl, o);
            sr += __shfl_xor_sync(0xffffffffu, sr, o);
        }
        xl[h] = sl; xr[h] = sr;
    }

    float s[H_];
    { float t = xl[0] + xr[0] + ba; s[0] = t >= 0.f ? t : 0.2f * t; }
#pragma unroll
    for (int i = 1; i < H_; i++) {
        float m = s[0];
        for (int h2 = 1; h2 < i; h2++) m = fmaxf(m, s[h2]);
        float den = 0.f, num = 0.f;
        for (int h2 = 0; h2 < i; h2++) {
            float e = __expf(s[h2] - m);
            den += e; num = fmaf(e, xl[h2], num);
        }
        float t = num / den + xr[i] + ba;
        s[i] = t >= 0.f ? t : 0.2f * t;
    }

    float m = s[0];
#pragma unroll
    for (int h2 = 1; h2 < H_; h2++) m = fmaxf(m, s[h2]);
    float e[H_], den = 0.f;
#pragma unroll
    for (int h2 = 0; h2 < H_; h2++) { e[h2] = __expf(s[h2] - m); den += e[h2]; }
    const float inv = 1.f / den;

#pragma unroll
    for (int j = 0; j < 4; j++) {
        float a0 = 0.f, a1 = 0.f;
#pragma unroll
        for (int h2 = 0; h2 < H_; h2++) {
            float w = e[h2] * inv;
            a0 = fmaf(w, v[h2][2*j], a0);
            a1 = fmaf(w, v[h2][2*j+1], a1);
        }
        __nv_bfloat16 h0, l0, h1, l1;
        splitf(a0, h0, l0); splitf(a1, h1, l1);
        rhi[(size_t)gw * 128 + lane + 32 * j] = pack2(h0, h1);
        rlo[(size_t)gw * 128 + lane + 32 * j] = pack2(l0, l1);
    }
}

// ============================================================================
// bf16x3 GEMM, 512 threads (16 warps, 4x4), tile 128x128, BK=32, double-
// buffered, ldmatrix fragment loads, TERM-OUTER mma order (same-acc reuse
// distance 8 -> no intra-warp RAW chains on accumulators).
// ============================================================================
template<int EPI>
__global__ __launch_bounds__(512)
void gemm512(const uint32_t* __restrict__ Ahi, const uint32_t* __restrict__ Alo, int ApW,
             const uint32_t* __restrict__ Bph, const uint32_t* __restrict__ Bpl, int Kp2,
             int ktiles,
             const float* __restrict__ bias, const float* __restrict__ Xin,
             float* __restrict__ Xout,
             uint32_t* __restrict__ Yhi, uint32_t* __restrict__ Ylo,
             float* __restrict__ outp, const float* __restrict__ alpha_p)
{
    extern __shared__ unsigned sh[];

    const int tid  = threadIdx.x;
    const int wid  = tid >> 5, lane = tid & 31;
    const int wr   = wid >> 2, wc = wid & 3;       // 4x4 warp grid
    const int g    = lane >> 2, t4 = lane & 3;
    const int rowBase = blockIdx.y * 128;
    const int colBase = blockIdx.x * 128;

    const uint32_t smem_base = smem_u32(sh);

    const int lm = lane >> 3, lr = lane & 7;
    int aIdx[2];
#pragma unroll
    for (int mi = 0; mi < 2; mi++)
        aIdx[mi] = (wr * 32 + mi * 16 + (lm & 1) * 8 + lr) * ASTR + (lm >> 1) * 4;
    const int bIdx = (wc * 32 + lm * 8 + lr) * ASTR;

    const int srow = tid >> 2, sq = tid & 3;
    const int aRowW = ApW >> 2;
    const int bRowW = Kp2 >> 2;

    const uint4* A4h = (const uint4*)Ahi;
    const uint4* A4l = (const uint4*)Alo;
    const uint4* B4h = (const uint4*)Bph;
    const uint4* B4l = (const uint4*)Bpl;

    float acc[2][4][4];
#pragma unroll
    for (int mi = 0; mi < 2; mi++)
#pragma unroll
        for (int ni = 0; ni < 4; ni++)
#pragma unroll
            for (int q = 0; q < 4; q++) acc[mi][ni][q] = 0.f;

    uint4 vAh, vAl, vBh, vBl;
    auto loadAB = [&](int kt) {
        size_t ai = (size_t)(rowBase + srow) * aRowW + kt * 4 + sq;
        size_t bi = (size_t)(colBase + srow) * bRowW + kt * 4 + sq;
        vAh = A4h[ai]; vAl = A4l[ai];
        vBh = B4h[bi]; vBl = B4l[bi];
    };
    auto stage = [&](int buf) {
        unsigned* base = sh + buf * BUFW;
        const int o = srow * 5 + sq;
        ((uint4*)(base          ))[o] = vAh;
        ((uint4*)(base + COMPW  ))[o] = vAl;
        ((uint4*)(base + 2*COMPW))[o] = vBh;
        ((uint4*)(base + 3*COMPW))[o] = vBl;
    };
    auto compute = [&](int buf) {
        const uint32_t bufo = smem_base + (uint32_t)buf * (BUFW * 4);
#pragma unroll
        for (int kk = 0; kk < 2; kk++) {
            const uint32_t koff = (uint32_t)(kk * 8 * 4);   // bytes
            unsigned ah[2][4], al[2][4];
#pragma unroll
            for (int mi = 0; mi < 2; mi++) {
                uint32_t aaddr = bufo + (uint32_t)(aIdx[mi] * 4) + koff;
                LDSM4(ah[mi][0], ah[mi][1], ah[mi][2], ah[mi][3], aaddr);
                LDSM4(al[mi][0], al[mi][1], al[mi][2], al[mi][3], aaddr + COMPW * 4);
            }
            unsigned bh0[4], bh1[4], bl0[4], bl1[4];
            {
                uint32_t baddr = bufo + (uint32_t)(2 * COMPW * 4) + (uint32_t)(bIdx * 4) + koff;
                LDSM4(bh0[0], bh0[1], bh0[2], bh0[3], baddr);
                LDSM4(bh1[0], bh1[1], bh1[2], bh1[3], baddr + 16);
                LDSM4(bl0[0], bl0[1], bl0[2], bl0[3], baddr + COMPW * 4);
                LDSM4(bl1[0], bl1[1], bl1[2], bl1[3], baddr + COMPW * 4 + 16);
            }
            // term-outer: consecutive mmas hit DIFFERENT accumulators
            // (same-acc reuse distance = 8 -> RAW latency fully hidden in-warp)
#pragma unroll
            for (int ni = 0; ni < 4; ni++)
#pragma unroll
                for (int mi = 0; mi < 2; mi++)
                    mma_bf16(acc[mi][ni], ah[mi], bh0[ni], bh1[ni]);  // hi*hi
#pragma unroll
            for (int ni = 0; ni < 4; ni++)
#pragma unroll
                for (int mi = 0; mi < 2; mi++)
                    mma_bf16(acc[mi][ni], ah[mi], bl0[ni], bl1[ni]);  // hi*lo
#pragma unroll
            for (int ni = 0; ni < 4; ni++)
#pragma unroll
                for (int mi = 0; mi < 2; mi++)
                    mma_bf16(acc[mi][ni], al[mi], bh0[ni], bh1[ni]);  // lo*hi
        }
    };

    // ---- pipelined mainloop: one sync per K-tile ----
    loadAB(0);
    stage(0);
    __syncthreads();
    if (ktiles > 1) loadAB(1);

    for (int kt = 0; kt < ktiles; kt++) {
        compute(kt & 1);
        if (kt + 1 < ktiles) {
            stage((kt + 1) & 1);
            __syncthreads();
            if (kt + 2 < ktiles) loadAB(kt + 2);
        }
    }

    // ---- epilogue ----
    float alpha = 0.f;
    if (EPI == 1 || EPI == 3 || EPI == 4 || EPI == 5) alpha = __ldg(alpha_p);

#pragma unroll
    for (int mi = 0; mi < 2; mi++) {
#pragma unroll
        for (int ni = 0; ni < 4; ni++) {
            const int r0 = rowBase + wr * 32 + mi * 16 + g;
            const int c0 = colBase + wc * 32 + ni * 8 + 2 * t4;
            if (EPI == 2 || EPI == 6) {
#pragma unroll
                for (int q = 0; q < 4; q++) {
                    int r = r0 + (q >= 2 ? 8 : 0);
                    int c = c0 + (q & 1);
                    if (c < C_ && r < NROWS) {
                        float t = acc[mi][ni][q] + __ldg(bias + c);
                        size_t idx = (size_t)r * C_ + c;
                        if (EPI == 6) t += outp[idx];
                        outp[idx] = t;
                    }
                }
            } else {
#pragma unroll
                for (int half = 0; half < 2; half++) {
                    const int r = r0 + half * 8;
                    float v0 = acc[mi][ni][half * 2 + 0];
                    float v1 = acc[mi][ni][half * 2 + 1];
                    float y0, y1;
                    if (EPI == 1) {
                        float t0 = v0 + __ldg(bias + c0);
                        float t1 = v1 + __ldg(bias + c0 + 1);
                        y0 = t0 >= 0.f ? t0 : alpha * t0;
                        y1 = t1 >= 0.f ? t1 : alpha * t1;
                    } else if (EPI == 3) {
                        float t0 = v0 + __ldg(bias + c0);
                        float t1 = v1 + __ldg(bias + c0 + 1);
                        Xout[(size_t)r * HIDD + c0]     = t0;
                        Xout[(size_t)r * HIDD + c0 + 1] = t1;
                        float p0 = t0 >= 0.f ? t0 : alpha * t0;
                        float p1 = t1 >= 0.f ? t1 : alpha * t1;
                        y0 = 0.5f * (p0 + t0);
                        y1 = 0.5f * (p1 + t1);
                    } else if (EPI == 4) {
                        float xa = Xin[(size_t)r * HIDD + c0];
                        float xb = Xin[(size_t)r * HIDD + c0 + 1];
                        float pa = xa >= 0.f ? xa : alpha * xa;
                        float pb = xb >= 0.f ? xb : alpha * xb;
                        float t0 = v0 + pa, t1 = v1 + pb;
                        float p0 = t0 >= 0.f ? t0 : alpha * t0;
                        float p1 = t1 >= 0.f ? t1 : alpha * t1;
                        Xout[(size_t)r * HIDD + c0]     = p0;
                        Xout[(size_t)r * HIDD + c0 + 1] = p1;
                        y0 = 0.5f * (p0 + xa);
                        y1 = 0.5f * (p1 + xb);
                    } else { // EPI == 5
                        float t0 = v0 + Xin[(size_t)r * HIDD + c0];
                        float t1 = v1 + Xin[(size_t)r * HIDD + c0 + 1];
                        y0 = t0 >= 0.f ? t0 : alpha * t0;
                        y1 = t1 >= 0.f ? t1 : alpha * t1;
                    }
                    __nv_bfloat16 h0, l0, h1, l1;
                    splitf(y0, h0, l0);
                    splitf(y1, h1, l1);
                    Yhi[(size_t)r * HIDDW + (c0 >> 1)] = pack2(h0, h1);
                    Ylo[(size_t)r * HIDDW + (c0 >> 1)] = pack2(l0, l1);
                }
            }
        }
    }
}

// ============================================================================
extern "C" void kernel_launch(void* const* d_in, const int* in_sizes, int n_in,
                              void* d_out, int out_size)
{
    (void)in_sizes; (void)n_in; (void)out_size;

    const float* features  = (const float*)d_in[0];
    const float* label_emb = (const float*)d_in[1];
    const float* wa        = (const float*)d_in[2];
    const float* ba        = (const float*)d_in[3];
    const float* w0        = (const float*)d_in[4];
    const float* b0        = (const float*)d_in[5];
    const float* wg1       = (const float*)d_in[6];
    const float* wg2       = (const float*)d_in[7];
    const float* w_last    = (const float*)d_in[8];
    const float* b_last    = (const float*)d_in[9];
    const float* a_out     = (const float*)d_in[10];
    const float* wl0       = (const float*)d_in[11];
    const float* bl0       = (const float*)d_in[12];
    const float* wl1       = (const float*)d_in[13];
    const float* bl1       = (const float*)d_in[14];
    const float* wl2       = (const float*)d_in[15];
    const float* bl2       = (const float*)d_in[16];
    const float* wl3       = (const float*)d_in[17];
    const float* bl3       = (const float*)d_in[18];
    const float* a_lab     = (const float*)d_in[19];
    float* out = (float*)d_out;

    uint32_t *Wph, *Wpl, *L0h, *L0l, *Ah, *Al, *Bh, *Bl, *Rh, *Rl;
    float *X1, *X2;
    cudaGetSymbolAddress((void**)&Wph, g_Wph);
    cudaGetSymbolAddress((void**)&Wpl, g_Wpl);
    cudaGetSymbolAddress((void**)&L0h, g_L0h);
    cudaGetSymbolAddress((void**)&L0l, g_L0l);
    cudaGetSymbolAddress((void**)&Ah,  g_Ah);
    cudaGetSymbolAddress((void**)&Al,  g_Al);
    cudaGetSymbolAddress((void**)&Bh,  g_Bh);
    cudaGetSymbolAddress((void**)&Bl,  g_Bl);
    cudaGetSymbolAddress((void**)&Rh,  g_Rh);
    cudaGetSymbolAddress((void**)&Rl,  g_Rl);
    cudaGetSymbolAddress((void**)&X1,  g_X1);
    cudaGetSymbolAddress((void**)&X2,  g_X2);

    cudaFuncSetAttribute(gemm512<1>, cudaFuncAttributeMaxDynamicSharedMemorySize, SMEM_DYN);
    cudaFuncSetAttribute(gemm512<2>, cudaFuncAttributeMaxDynamicSharedMemorySize, SMEM_DYN);
    cudaFuncSetAttribute(gemm512<3>, cudaFuncAttributeMaxDynamicSharedMemorySize, SMEM_DYN);
    cudaFuncSetAttribute(gemm512<4>, cudaFuncAttributeMaxDynamicSharedMemorySize, SMEM_DYN);
    cudaFuncSetAttribute(gemm512<5>, cudaFuncAttributeMaxDynamicSharedMemorySize, SMEM_DYN);
    cudaFuncSetAttribute(gemm512<6>, cudaFuncAttributeMaxDynamicSharedMemorySize, SMEM_DYN);

    dim3 blk(256);
    auto cwg = [](size_t n) { return dim3((unsigned)((n + 255) / 256)); };
    dim3 tblk(512);
    dim3 g512(4, MPAD / 128);
    dim3 g47(1, MPAD / 128);

    // Launch order interleaves conversions and label-branch GEMMs so that the
    // 6th launch (ncu -s 5 -c 1 window) is a full K=512 gemm512<1>.
    // Dependencies: each gemm's operands are produced by earlier launches.

    convl_kernel<<<cwg((size_t)MPAD * 32), blk>>>(label_emb, L0h, L0l);                               // 1
    convw_kernel<<<cwg(512 *  32), blk>>>(wl0,    Wph + O_wl0,   Wpl + O_wl0,   C_,   HIDD,  32, 512); // 2
    convw_kernel<<<cwg(512 * 256), blk>>>(wl1,    Wph + O_wl1,   Wpl + O_wl1,   HIDD, HIDD, 256, 512); // 3
    gemm512<1><<<g512, tblk, SMEM_DYN>>>(L0h, L0l, 32,  Wph + O_wl0, Wpl + O_wl0, 32,  2,              // 4
                                         bl0, nullptr, nullptr, Ah, Al, nullptr, a_lab);
    convw_kernel<<<cwg(512 * 256), blk>>>(wl2,    Wph + O_wl2,   Wpl + O_wl2,   HIDD, HIDD, 256, 512); // 5
    gemm512<1><<<g512, tblk, SMEM_DYN>>>(Ah, Al, 256, Wph + O_wl1, Wpl + O_wl1, 256, 16,               // 6 <- profiled
                                         bl1, nullptr, nullptr, Bh, Bl, nullptr, a_lab);
    convw_kernel<<<cwg(128 * 256), blk>>>(wl3,    Wph + O_wl3,   Wpl + O_wl3,   HIDD, C_,   256, 128); // 7
    gemm512<1><<<g512, tblk, SMEM_DYN>>>(Bh, Bl, 256, Wph + O_wl2, Wpl + O_wl2, 256, 16,               // 8
                                         bl2, nullptr, nullptr, Ah, Al, nullptr, a_lab);
    gemm512<2><<<g47,  tblk, SMEM_DYN>>>(Ah, Al, 256, Wph + O_wl3, Wpl + O_wl3, 256, 16,               // 9
                                         bl3, nullptr, nullptr, nullptr, nullptr, out, nullptr);

    att_kernel<<<dim3(MPAD / 8), blk>>>(features, wa, ba, Rh, Rl);                                     // 10
    convw_kernel<<<cwg(512 * 128), blk>>>(w0,     Wph + O_w0,    Wpl + O_w0,    F_,   HIDD, 128, 512); // 11
    gemm512<3><<<g512, tblk, SMEM_DYN>>>(Rh, Rl, 128, Wph + O_w0, Wpl + O_w0, 128, 8,                  // 12
                                         b0, nullptr, X1, Bh, Bl, nullptr, a_out);
    convw_kernel<<<cwg(512 * 256), blk>>>(wg1,    Wph + O_wg1,   Wpl + O_wg1,   HIDD, HIDD, 256, 512); // 13
    gemm512<4><<<g512, tblk, SMEM_DYN>>>(Bh, Bl, 256, Wph + O_wg1, Wpl + O_wg1, 256, 16,               // 14
                                         nullptr, X1, X2, Ah, Al, nullptr, a_out);
    convw_kernel<<<cwg(512 * 256), blk>>>(wg2,    Wph + O_wg2,   Wpl + O_wg2,   HIDD, HIDD, 256, 512); // 15
    gemm512<5><<<g512, tblk, SMEM_DYN>>>(Ah, Al, 256, Wph + O_wg2, Wpl + O_wg2, 256, 16,               // 16
                                         nullptr, X2, nullptr, Bh, Bl, nullptr, a_out);
    convw_kernel<<<cwg(128 * 256), blk>>>(w_last, Wph + O_wlast, Wpl + O_wlast, HIDD, C_,   256, 128); // 17
    gemm512<6><<<g47,  tblk, SMEM_DYN>>>(Bh, Bl, 256, Wph + O_wlast, Wpl + O_wlast, 256, 16,           // 18
                                         b_last, nullptr, nullptr, nullptr, nullptr, out, a_out);
}